// round 13
// baseline (speedup 1.0000x reference)
#include <cuda_runtime.h>
#include <cuda_fp16.h>
#include <cstdint>

#define B_DIM   512
#define E_DIM   8
#define IN_DIM  1024
#define OUT_DIM 1024

#define MT 128
#define NT 128
#define KC 64                        // K chunk (fp16) = 128B row
#define NCHUNK (IN_DIM / KC)         // 16
#define THREADS 256

#define TILE_BYTES (128 * 128)       // 16KB per operand tile
#define BUFSZ (2 * TILE_BYTES)       // A + B
#define SMEM_TOTAL (2 * BUFSZ)       // 64KB double-buffered

#define X_BLOCKS     256             // prep_x blocks (8 elems/thread)
#define CONV_PER_E   128             // conv blocks per expert (32 elems/thread)
#define GEMM_PER_E   32              // (8 bn x 4 bm)
#define GRP          (CONV_PER_E + GEMM_PER_E)
#define TOTAL_BLOCKS (X_BLOCKS + E_DIM * GRP)   // 1536

// scratch (no cudaMalloc allowed)
__device__ __half g_xs[E_DIM * B_DIM * IN_DIM];      // pre-blended A planes, 8MB
__device__ __half g_wh[E_DIM * OUT_DIM * IN_DIM];    // fp16 W, 16.8MB
__device__ float  g_partial[E_DIM * B_DIM * OUT_DIM];
__device__ int    g_flag_x;
__device__ int    g_flag_w[E_DIM];

// ---------- helpers ----------
__device__ __forceinline__ uint32_t smem_u32(const void* p) {
    uint32_t a;
    asm("{ .reg .u64 t; cvta.to.shared.u64 t, %1; cvt.u32.u64 %0, t; }" : "=r"(a) : "l"(p));
    return a;
}
__device__ __forceinline__ void cp16(uint32_t dst, const void* src) {
    asm volatile("cp.async.cg.shared.global [%0], [%1], 16;" :: "r"(dst), "l"(src));
}
__device__ __forceinline__ void ldsm_x4(uint32_t* r, uint32_t addr) {
    asm volatile("ldmatrix.sync.aligned.m8n8.x4.shared.b16 {%0,%1,%2,%3}, [%4];"
                 : "=r"(r[0]), "=r"(r[1]), "=r"(r[2]), "=r"(r[3]) : "r"(addr));
}
__device__ __forceinline__ void mma_fp16(float* c, const uint32_t* a,
                                         uint32_t b0, uint32_t b1) {
    asm volatile(
        "mma.sync.aligned.m16n8k16.row.col.f32.f16.f16.f32 "
        "{%0,%1,%2,%3}, {%4,%5,%6,%7}, {%8,%9}, {%0,%1,%2,%3};"
        : "+f"(c[0]), "+f"(c[1]), "+f"(c[2]), "+f"(c[3])
        : "r"(a[0]), "r"(a[1]), "r"(a[2]), "r"(a[3]), "r"(b0), "r"(b1));
}
__device__ __forceinline__ uint32_t sw_off(int r, int kb) {
    return (uint32_t)(r * 128 + ((kb ^ (r & 7)) << 4));
}

// ---------- flag reset (runs before mega each launch) ----------
__global__ void reset_kernel()
{
    if (threadIdx.x == 0) g_flag_x = 0;
    if (threadIdx.x < E_DIM) g_flag_w[threadIdx.x] = 0;
}

// ---------- mega: prepX + per-expert {convW, GEMM} with flag sync ----------
__global__ __launch_bounds__(THREADS, 2)
void mega_kernel(const float* __restrict__ x,
                 const float* __restrict__ ew,
                 const float* __restrict__ W)
{
    extern __shared__ __align__(16) uint8_t smem[];
    const int bid = blockIdx.x;
    const int tid = threadIdx.x;

    // ============ prep_x blocks ============
    if (bid < X_BLOCKS) {
        const int idx = (bid * 256 + tid) * 8;
        const int b = idx >> 10;
        const float4 v0 = __ldg((const float4*)(x + idx));
        const float4 v1 = __ldg((const float4*)(x + idx + 4));
        #pragma unroll
        for (int e = 0; e < E_DIM; ++e) {
            const float s = __ldg(&ew[b * E_DIM + e]);
            __half2 a = __floats2half2_rn(v0.x * s, v0.y * s);
            __half2 c = __floats2half2_rn(v0.z * s, v0.w * s);
            __half2 d = __floats2half2_rn(v1.x * s, v1.y * s);
            __half2 f = __floats2half2_rn(v1.z * s, v1.w * s);
            *(uint4*)(g_xs + (size_t)e * (B_DIM * IN_DIM) + idx) =
                make_uint4(*(uint32_t*)&a, *(uint32_t*)&c,
                           *(uint32_t*)&d, *(uint32_t*)&f);
        }
        __syncthreads();
        if (tid == 0) { __threadfence(); atomicAdd(&g_flag_x, 1); }
        return;
    }

    const int g = bid - X_BLOCKS;
    const int e = g / GRP;
    const int r = g % GRP;

    // ============ conv_W blocks (32 elems/thread) ============
    if (r < CONV_PER_E) {
        const size_t base = (size_t)e * (OUT_DIM * IN_DIM) + ((size_t)r * 256 + tid) * 32;
        float4 v[8];
        #pragma unroll
        for (int j = 0; j < 8; ++j) v[j] = __ldg((const float4*)(W + base + 4 * j));
        #pragma unroll
        for (int j = 0; j < 4; ++j) {
            __half2 a = __floats2half2_rn(v[2*j].x,   v[2*j].y);
            __half2 b = __floats2half2_rn(v[2*j].z,   v[2*j].w);
            __half2 c = __floats2half2_rn(v[2*j+1].x, v[2*j+1].y);
            __half2 d = __floats2half2_rn(v[2*j+1].z, v[2*j+1].w);
            *(uint4*)(g_wh + base + 8 * j) =
                make_uint4(*(uint32_t*)&a, *(uint32_t*)&b,
                           *(uint32_t*)&c, *(uint32_t*)&d);
        }
        __syncthreads();
        if (tid == 0) { __threadfence(); atomicAdd(&g_flag_w[e], 1); }
        return;
    }

    // ============ GEMM blocks ============
    const int gb = r - CONV_PER_E;       // 0..31
    const int bn = (gb & 7) * NT;
    const int bm = (gb >> 3) * MT;

    // wait for this expert's W conversion and the x blend
    if (tid == 0) {
        while (*(volatile int*)&g_flag_w[e] < CONV_PER_E) { }
        while (*(volatile int*)&g_flag_x < X_BLOCKS) { }
        __threadfence();
    }
    __syncthreads();

    const uint32_t sbase = smem_u32(smem);
    const int lane = tid & 31;
    const int wid  = tid >> 5;
    const int wm = wid >> 2;        // 0..1 -> 64 rows
    const int wn = wid & 3;         // 0..3 -> 32 cols

    const __half* ap = g_xs + (size_t)e * (B_DIM * IN_DIM);
    const __half* bp = g_wh + (size_t)e * (OUT_DIM * IN_DIM);

    float acc[16][4];
    #pragma unroll
    for (int i = 0; i < 16; ++i)
        #pragma unroll
        for (int j = 0; j < 4; ++j) acc[i][j] = 0.0f;

    auto issue = [&](int c, int buf) {
        const int k0 = c * KC;
        const uint32_t base = sbase + buf * BUFSZ;
        #pragma unroll
        for (int j = 0; j < 4; ++j) {
            const int cid = tid + j * 256;     // 0..1023
            const int row = cid >> 3;
            const int kb  = cid & 7;
            const uint32_t d = sw_off(row, kb);
            const int goff = k0 + kb * 8;
            cp16(base + d,              ap + (size_t)(bm + row) * IN_DIM + goff);
            cp16(base + TILE_BYTES + d, bp + (size_t)(bn + row) * IN_DIM + goff);
        }
        asm volatile("cp.async.commit_group;" ::: "memory");
    };

    issue(0, 0);

    for (int c = 0; c < NCHUNK; ++c) {
        const int buf = c & 1;
        if (c + 1 < NCHUNK) {
            issue(c + 1, buf ^ 1);
            asm volatile("cp.async.wait_group 1;" ::: "memory");
        } else {
            asm volatile("cp.async.wait_group 0;" ::: "memory");
        }
        __syncthreads();

        const uint32_t uA = sbase + buf * BUFSZ;
        const uint32_t uB = uA + TILE_BYTES;

        #pragma unroll
        for (int ks = 0; ks < 4; ++ks) {
            uint32_t ah[4][4];
            const int ar  = lane & 15;
            const int akb = ks * 2 + (lane >> 4);
            #pragma unroll
            for (int mt = 0; mt < 4; ++mt) {
                const int rr = wm * 64 + mt * 16 + ar;
                ldsm_x4(ah[mt], uA + sw_off(rr, akb));
            }
            uint32_t bh[2][4];
            #pragma unroll
            for (int p = 0; p < 2; ++p) {
                const int rr = wn * 32 + p * 16 + (lane & 7) + ((lane >> 4) & 1) * 8;
                const int kb = ks * 2 + ((lane >> 3) & 1);
                ldsm_x4(bh[p], uB + sw_off(rr, kb));
            }
            #pragma unroll
            for (int mt = 0; mt < 4; ++mt)
                #pragma unroll
                for (int p = 0; p < 2; ++p)
                    #pragma unroll
                    for (int sub = 0; sub < 2; ++sub)
                        mma_fp16(acc[mt * 4 + p * 2 + sub], ah[mt],
                                 bh[p][sub * 2], bh[p][sub * 2 + 1]);
        }
        __syncthreads();
    }

    // epilogue -> partial plane e
    const int tr = lane >> 2;
    const int tc = (lane & 3) * 2;
    #pragma unroll
    for (int mt = 0; mt < 4; ++mt) {
        const int row = bm + wm * 64 + mt * 16 + tr;
        float* base = g_partial + ((size_t)e * B_DIM + row) * OUT_DIM + bn + wn * 32;
        #pragma unroll
        for (int nt = 0; nt < 4; ++nt) {
            const float* a4 = acc[mt * 4 + nt];
            *(float2*)(base + nt * 8 + tc)                       = make_float2(a4[0], a4[1]);
            *(float2*)(base + 8 * (size_t)OUT_DIM + nt * 8 + tc) = make_float2(a4[2], a4[3]);
        }
    }
}

// ---------- combine: sum 8 partial planes + blended bias (2 floats/thread) ----------
__global__ __launch_bounds__(256)
void combine_kernel(const float* __restrict__ ew,
                    const float* __restrict__ bias,
                    float* __restrict__ out)
{
    const int idx = (blockIdx.x * 256 + threadIdx.x) * 2;
    const int b   = idx >> 10;
    const int o   = idx & 1023;
    const size_t off = (size_t)b * OUT_DIM + o;
    const size_t plane = (size_t)B_DIM * OUT_DIM;

    float2 p[E_DIM];
    #pragma unroll
    for (int e = 0; e < E_DIM; ++e)
        p[e] = *(const float2*)&g_partial[e * plane + off];

    float2 bv[E_DIM];
    #pragma unroll
    for (int e = 0; e < E_DIM; ++e)
        bv[e] = *(const float2*)&bias[e * OUT_DIM + o];

    float w[E_DIM];
    #pragma unroll
    for (int e = 0; e < E_DIM; ++e) w[e] = __ldg(&ew[b * E_DIM + e]);

    float sx = 0.f, sy = 0.f;
    #pragma unroll
    for (int e = 0; e < E_DIM; ++e) { sx += p[e].x; sy += p[e].y; }
    #pragma unroll
    for (int e = 0; e < E_DIM; ++e) {
        sx = fmaf(w[e], bv[e].x, sx);
        sy = fmaf(w[e], bv[e].y, sy);
    }
    *(float2*)(out + off) = make_float2(sx, sy);
}

extern "C" void kernel_launch(void* const* d_in, const int* in_sizes, int n_in,
                              void* d_out, int out_size)
{
    const float* x    = (const float*)d_in[0];   // [512, 1024]
    const float* ew   = (const float*)d_in[1];   // [512, 8]
    const float* W    = (const float*)d_in[2];   // [8, 1024, 1024]
    const float* bias = (const float*)d_in[3];   // [8, 1024]
    float* out = (float*)d_out;

    cudaFuncSetAttribute(mega_kernel,
                         cudaFuncAttributeMaxDynamicSharedMemorySize, SMEM_TOTAL);

    reset_kernel<<<1, 32>>>();
    mega_kernel<<<TOTAL_BLOCKS, THREADS, SMEM_TOTAL>>>(x, ew, W);
    combine_kernel<<<B_DIM * OUT_DIM / 2 / 256, 256>>>(ew, bias, out);
}

// round 15
// speedup vs baseline: 1.4217x; 1.4217x over previous
#include <cuda_runtime.h>
#include <cuda_fp16.h>
#include <cstdint>

#define B_DIM   512
#define E_DIM   8
#define IN_DIM  1024
#define OUT_DIM 1024

#define MT 128
#define NT 128
#define KC 64                        // K chunk (fp16) = 128B row
#define NCHUNK (IN_DIM / KC)         // 16
#define THREADS 256

#define TILE_BYTES (128 * 128)       // 16KB per operand tile
#define BUFSZ (2 * TILE_BYTES)       // A + B
#define SMEM_TOTAL (2 * BUFSZ)       // 64KB double-buffered

// scratch (no cudaMalloc allowed)
__device__ __half g_xh[B_DIM * IN_DIM];              // fp16 x, 1MB (unblended)
__device__ __half g_wh[E_DIM * OUT_DIM * IN_DIM];    // fp16 W, 16.8MB
__device__ float  g_partial[E_DIM * B_DIM * OUT_DIM];

// ---------- helpers ----------
__device__ __forceinline__ uint32_t smem_u32(const void* p) {
    uint32_t a;
    asm("{ .reg .u64 t; cvta.to.shared.u64 t, %1; cvt.u32.u64 %0, t; }" : "=r"(a) : "l"(p));
    return a;
}
__device__ __forceinline__ void cp16(uint32_t dst, const void* src) {
    asm volatile("cp.async.cg.shared.global [%0], [%1], 16;" :: "r"(dst), "l"(src));
}
__device__ __forceinline__ void ldsm_x4(uint32_t* r, uint32_t addr) {
    asm volatile("ldmatrix.sync.aligned.m8n8.x4.shared.b16 {%0,%1,%2,%3}, [%4];"
                 : "=r"(r[0]), "=r"(r[1]), "=r"(r[2]), "=r"(r[3]) : "r"(addr));
}
__device__ __forceinline__ void mma_fp16(float* c, const uint32_t* a,
                                         uint32_t b0, uint32_t b1) {
    asm volatile(
        "mma.sync.aligned.m16n8k16.row.col.f32.f16.f16.f32 "
        "{%0,%1,%2,%3}, {%4,%5,%6,%7}, {%8,%9}, {%0,%1,%2,%3};"
        : "+f"(c[0]), "+f"(c[1]), "+f"(c[2]), "+f"(c[3])
        : "r"(a[0]), "r"(a[1]), "r"(a[2]), "r"(a[3]), "r"(b0), "r"(b1));
}
__device__ __forceinline__ uint32_t sw_off(int r, int kb) {
    return (uint32_t)(r * 128 + ((kb ^ (r & 7)) << 4));
}

// ---------- prep: W->fp16 (8 elems/thread) and x->fp16 ----------
#define W_BLOCKS (E_DIM * OUT_DIM * IN_DIM / 8 / 256)   // 4096
#define X_BLOCKS (B_DIM * IN_DIM / 8 / 256)             // 256
__global__ __launch_bounds__(256)
void prep_kernel(const float* __restrict__ x,
                 const float* __restrict__ W)
{
    if (blockIdx.x < W_BLOCKS) {
        const size_t idx = ((size_t)blockIdx.x * 256 + threadIdx.x) * 8;
        const float4 v0 = __ldg((const float4*)(W + idx));
        const float4 v1 = __ldg((const float4*)(W + idx + 4));
        __half2 a = __floats2half2_rn(v0.x, v0.y);
        __half2 b = __floats2half2_rn(v0.z, v0.w);
        __half2 c = __floats2half2_rn(v1.x, v1.y);
        __half2 d = __floats2half2_rn(v1.z, v1.w);
        *(uint4*)(g_wh + idx) = make_uint4(*(uint32_t*)&a, *(uint32_t*)&b,
                                           *(uint32_t*)&c, *(uint32_t*)&d);
    } else {
        const int idx = ((blockIdx.x - W_BLOCKS) * 256 + threadIdx.x) * 8;
        const float4 v0 = __ldg((const float4*)(x + idx));
        const float4 v1 = __ldg((const float4*)(x + idx + 4));
        __half2 a = __floats2half2_rn(v0.x, v0.y);
        __half2 c = __floats2half2_rn(v0.z, v0.w);
        __half2 d = __floats2half2_rn(v1.x, v1.y);
        __half2 f = __floats2half2_rn(v1.z, v1.w);
        *(uint4*)(g_xh + idx) = make_uint4(*(uint32_t*)&a, *(uint32_t*)&c,
                                           *(uint32_t*)&d, *(uint32_t*)&f);
    }
}

// ---------- GEMM: plane_e = x @ W_e^T (unblended) ----------
__global__ __launch_bounds__(THREADS, 2)
void moe_gemm_kernel()
{
    extern __shared__ __align__(16) uint8_t smem[];
    const uint32_t sbase = smem_u32(smem);

    const int tid  = threadIdx.x;
    const int lane = tid & 31;
    const int wid  = tid >> 5;
    const int bn = blockIdx.x * NT;
    const int bm = blockIdx.y * MT;
    const int e  = blockIdx.z;

    const int wm = wid >> 2;        // 0..1 -> 64 rows
    const int wn = wid & 3;         // 0..3 -> 32 cols

    const __half* ap = g_xh;
    const __half* bp = g_wh + (size_t)e * (OUT_DIM * IN_DIM);

    float acc[16][4];
    #pragma unroll
    for (int i = 0; i < 16; ++i)
        #pragma unroll
        for (int j = 0; j < 4; ++j) acc[i][j] = 0.0f;

    auto issue = [&](int c, int buf) {
        const int k0 = c * KC;
        const uint32_t base = sbase + buf * BUFSZ;
        #pragma unroll
        for (int j = 0; j < 4; ++j) {
            const int cid = tid + j * 256;     // 0..1023
            const int row = cid >> 3;
            const int kb  = cid & 7;
            const uint32_t d = sw_off(row, kb);
            const int goff = k0 + kb * 8;
            cp16(base + d,              ap + (size_t)(bm + row) * IN_DIM + goff);
            cp16(base + TILE_BYTES + d, bp + (size_t)(bn + row) * IN_DIM + goff);
        }
        asm volatile("cp.async.commit_group;" ::: "memory");
    };

    issue(0, 0);

    for (int c = 0; c < NCHUNK; ++c) {
        const int buf = c & 1;
        if (c + 1 < NCHUNK) {
            issue(c + 1, buf ^ 1);
            asm volatile("cp.async.wait_group 1;" ::: "memory");
        } else {
            asm volatile("cp.async.wait_group 0;" ::: "memory");
        }
        __syncthreads();

        const uint32_t uA = sbase + buf * BUFSZ;
        const uint32_t uB = uA + TILE_BYTES;

        #pragma unroll
        for (int ks = 0; ks < 4; ++ks) {
            uint32_t ah[4][4];
            const int ar  = lane & 15;
            const int akb = ks * 2 + (lane >> 4);
            #pragma unroll
            for (int mt = 0; mt < 4; ++mt) {
                const int r = wm * 64 + mt * 16 + ar;
                ldsm_x4(ah[mt], uA + sw_off(r, akb));
            }
            uint32_t bh[2][4];
            #pragma unroll
            for (int p = 0; p < 2; ++p) {
                const int r  = wn * 32 + p * 16 + (lane & 7) + ((lane >> 4) & 1) * 8;
                const int kb = ks * 2 + ((lane >> 3) & 1);
                ldsm_x4(bh[p], uB + sw_off(r, kb));
            }
            #pragma unroll
            for (int mt = 0; mt < 4; ++mt)
                #pragma unroll
                for (int p = 0; p < 2; ++p)
                    #pragma unroll
                    for (int sub = 0; sub < 2; ++sub)
                        mma_fp16(acc[mt * 4 + p * 2 + sub], ah[mt],
                                 bh[p][sub * 2], bh[p][sub * 2 + 1]);
        }
        __syncthreads();
    }

    // epilogue -> plane e
    const int tr = lane >> 2;
    const int tc = (lane & 3) * 2;
    #pragma unroll
    for (int mt = 0; mt < 4; ++mt) {
        const int row = bm + wm * 64 + mt * 16 + tr;
        float* base = g_partial + ((size_t)e * B_DIM + row) * OUT_DIM + bn + wn * 32;
        #pragma unroll
        for (int nt = 0; nt < 4; ++nt) {
            const float* a4 = acc[mt * 4 + nt];
            *(float2*)(base + nt * 8 + tc)                       = make_float2(a4[0], a4[1]);
            *(float2*)(base + 8 * (size_t)OUT_DIM + nt * 8 + tc) = make_float2(a4[2], a4[3]);
        }
    }
}

// ---------- combine: out = sum_e w_e*(plane_e + bias_e) (4 floats/thread) ----------
__global__ __launch_bounds__(256)
void combine_kernel(const float* __restrict__ ew,
                    const float* __restrict__ bias,
                    float* __restrict__ out)
{
    const int idx = (blockIdx.x * 256 + threadIdx.x) * 4;
    const int b   = idx >> 10;
    const int o   = idx & 1023;
    const size_t off = (size_t)b * OUT_DIM + o;
    const size_t plane = (size_t)B_DIM * OUT_DIM;

    float4 p[E_DIM];
    #pragma unroll
    for (int e = 0; e < E_DIM; ++e)
        p[e] = *(const float4*)&g_partial[e * plane + off];

    float w[E_DIM];
    #pragma unroll
    for (int e = 0; e < E_DIM; ++e) w[e] = __ldg(&ew[b * E_DIM + e]);

    float4 s = make_float4(0.f, 0.f, 0.f, 0.f);
    #pragma unroll
    for (int e = 0; e < E_DIM; ++e) {
        s.x = fmaf(w[e], p[e].x, s.x);
        s.y = fmaf(w[e], p[e].y, s.y);
        s.z = fmaf(w[e], p[e].z, s.z);
        s.w = fmaf(w[e], p[e].w, s.w);
    }
    #pragma unroll
    for (int e = 0; e < E_DIM; ++e) {
        const float4 bv = *(const float4*)&bias[e * OUT_DIM + o];
        s.x = fmaf(w[e], bv.x, s.x); s.y = fmaf(w[e], bv.y, s.y);
        s.z = fmaf(w[e], bv.z, s.z); s.w = fmaf(w[e], bv.w, s.w);
    }
    *(float4*)(out + off) = s;
}

extern "C" void kernel_launch(void* const* d_in, const int* in_sizes, int n_in,
                              void* d_out, int out_size)
{
    const float* x    = (const float*)d_in[0];   // [512, 1024]
    const float* ew   = (const float*)d_in[1];   // [512, 8]
    const float* W    = (const float*)d_in[2];   // [8, 1024, 1024]
    const float* bias = (const float*)d_in[3];   // [8, 1024]
    float* out = (float*)d_out;

    prep_kernel<<<W_BLOCKS + X_BLOCKS, 256>>>(x, W);

    cudaFuncSetAttribute(moe_gemm_kernel,
                         cudaFuncAttributeMaxDynamicSharedMemorySize, SMEM_TOTAL);
    dim3 grid(OUT_DIM / NT, B_DIM / MT, E_DIM);   // (8, 4, 8) = 256 CTAs
    moe_gemm_kernel<<<grid, THREADS, SMEM_TOTAL>>>();

    combine_kernel<<<B_DIM * OUT_DIM / 4 / 256, 256>>>(ew, bias, out);
}

// round 16
// speedup vs baseline: 1.4721x; 1.0355x over previous
#include <cuda_runtime.h>
#include <cuda_fp16.h>
#include <cstdint>

#define B_DIM   512
#define E_DIM   8
#define IN_DIM  1024
#define OUT_DIM 1024

#define MT 128
#define NT 128
#define KC 64                        // K chunk (fp16) = 128B row
#define NCHUNK (IN_DIM / KC)         // 16
#define THREADS 256

#define TILE_BYTES (128 * 128)       // 16KB per operand tile
#define BUFSZ (2 * TILE_BYTES)       // A + B
#define SMEM_TOTAL (2 * BUFSZ)       // 64KB double-buffered

// scratch (no cudaMalloc allowed)
__device__ __half g_xh[B_DIM * IN_DIM];              // fp16 x, 1MB
__device__ __half g_wh[E_DIM * OUT_DIM * IN_DIM];    // fp16 W, 16.8MB

// ---------- helpers ----------
__device__ __forceinline__ uint32_t smem_u32(const void* p) {
    uint32_t a;
    asm("{ .reg .u64 t; cvta.to.shared.u64 t, %1; cvt.u32.u64 %0, t; }" : "=r"(a) : "l"(p));
    return a;
}
__device__ __forceinline__ void cp16(uint32_t dst, const void* src) {
    asm volatile("cp.async.cg.shared.global [%0], [%1], 16;" :: "r"(dst), "l"(src));
}
__device__ __forceinline__ void ldsm_x4(uint32_t* r, uint32_t addr) {
    asm volatile("ldmatrix.sync.aligned.m8n8.x4.shared.b16 {%0,%1,%2,%3}, [%4];"
                 : "=r"(r[0]), "=r"(r[1]), "=r"(r[2]), "=r"(r[3]) : "r"(addr));
}
__device__ __forceinline__ void mma_fp16(float* c, const uint32_t* a,
                                         uint32_t b0, uint32_t b1) {
    asm volatile(
        "mma.sync.aligned.m16n8k16.row.col.f32.f16.f16.f32 "
        "{%0,%1,%2,%3}, {%4,%5,%6,%7}, {%8,%9}, {%0,%1,%2,%3};"
        : "+f"(c[0]), "+f"(c[1]), "+f"(c[2]), "+f"(c[3])
        : "r"(a[0]), "r"(a[1]), "r"(a[2]), "r"(a[3]), "r"(b0), "r"(b1));
}
__device__ __forceinline__ uint32_t sw_off(int r, int kb) {
    return (uint32_t)(r * 128 + ((kb ^ (r & 7)) << 4));
}
__device__ __forceinline__ void redadd(float* p, float v) {
    asm volatile("red.global.add.f32 [%0], %1;" :: "l"(p), "f"(v) : "memory");
}

// ---------- prep: W->fp16, x->fp16, out = blended bias ----------
#define W_BLOCKS (E_DIM * OUT_DIM * IN_DIM / 8 / 256)   // 4096
#define X_BLOCKS (B_DIM * IN_DIM / 8 / 256)             // 256
#define O_BLOCKS (B_DIM * OUT_DIM / 4 / 256)            // 512
__global__ __launch_bounds__(256)
void prep_kernel(const float* __restrict__ x,
                 const float* __restrict__ ew,
                 const float* __restrict__ W,
                 const float* __restrict__ bias,
                 float* __restrict__ out)
{
    if (blockIdx.x < W_BLOCKS) {
        const size_t idx = ((size_t)blockIdx.x * 256 + threadIdx.x) * 8;
        const float4 v0 = __ldg((const float4*)(W + idx));
        const float4 v1 = __ldg((const float4*)(W + idx + 4));
        __half2 a = __floats2half2_rn(v0.x, v0.y);
        __half2 b = __floats2half2_rn(v0.z, v0.w);
        __half2 c = __floats2half2_rn(v1.x, v1.y);
        __half2 d = __floats2half2_rn(v1.z, v1.w);
        *(uint4*)(g_wh + idx) = make_uint4(*(uint32_t*)&a, *(uint32_t*)&b,
                                           *(uint32_t*)&c, *(uint32_t*)&d);
    } else if (blockIdx.x < W_BLOCKS + X_BLOCKS) {
        const int idx = ((blockIdx.x - W_BLOCKS) * 256 + threadIdx.x) * 8;
        const float4 v0 = __ldg((const float4*)(x + idx));
        const float4 v1 = __ldg((const float4*)(x + idx + 4));
        __half2 a = __floats2half2_rn(v0.x, v0.y);
        __half2 c = __floats2half2_rn(v0.z, v0.w);
        __half2 d = __floats2half2_rn(v1.x, v1.y);
        __half2 f = __floats2half2_rn(v1.z, v1.w);
        *(uint4*)(g_xh + idx) = make_uint4(*(uint32_t*)&a, *(uint32_t*)&c,
                                           *(uint32_t*)&d, *(uint32_t*)&f);
    } else {
        // out = sum_e ew[b,e] * bias[e,o]
        const int idx = ((blockIdx.x - W_BLOCKS - X_BLOCKS) * 256 + threadIdx.x) * 4;
        const int b = idx >> 10;
        const int o = idx & 1023;
        float w[E_DIM];
        #pragma unroll
        for (int e = 0; e < E_DIM; ++e) w[e] = __ldg(&ew[b * E_DIM + e]);
        float4 s = make_float4(0.f, 0.f, 0.f, 0.f);
        #pragma unroll
        for (int e = 0; e < E_DIM; ++e) {
            const float4 bv = __ldg((const float4*)&bias[e * OUT_DIM + o]);
            s.x = fmaf(w[e], bv.x, s.x); s.y = fmaf(w[e], bv.y, s.y);
            s.z = fmaf(w[e], bv.z, s.z); s.w = fmaf(w[e], bv.w, s.w);
        }
        *(float4*)(out + (size_t)b * OUT_DIM + o) = s;
    }
}

// ---------- GEMM: out += ew[:,e] * (x @ W_e^T), via red.global ----------
__global__ __launch_bounds__(THREADS, 2)
void moe_gemm_kernel(const float* __restrict__ ew,
                     float* __restrict__ out)
{
    extern __shared__ __align__(16) uint8_t smem[];
    const uint32_t sbase = smem_u32(smem);

    const int tid  = threadIdx.x;
    const int lane = tid & 31;
    const int wid  = tid >> 5;
    const int bn = blockIdx.x * NT;
    const int bm = blockIdx.y * MT;
    const int e  = blockIdx.z;

    const int wm = wid >> 2;        // 0..1 -> 64 rows
    const int wn = wid & 3;         // 0..3 -> 32 cols

    const __half* ap = g_xh;
    const __half* bp = g_wh + (size_t)e * (OUT_DIM * IN_DIM);

    float acc[16][4];
    #pragma unroll
    for (int i = 0; i < 16; ++i)
        #pragma unroll
        for (int j = 0; j < 4; ++j) acc[i][j] = 0.0f;

    auto issue = [&](int c, int buf) {
        const int k0 = c * KC;
        const uint32_t base = sbase + buf * BUFSZ;
        #pragma unroll
        for (int j = 0; j < 4; ++j) {
            const int cid = tid + j * 256;     // 0..1023
            const int row = cid >> 3;
            const int kb  = cid & 7;
            const uint32_t d = sw_off(row, kb);
            const int goff = k0 + kb * 8;
            cp16(base + d,              ap + (size_t)(bm + row) * IN_DIM + goff);
            cp16(base + TILE_BYTES + d, bp + (size_t)(bn + row) * IN_DIM + goff);
        }
        asm volatile("cp.async.commit_group;" ::: "memory");
    };

    issue(0, 0);

    for (int c = 0; c < NCHUNK; ++c) {
        const int buf = c & 1;
        if (c + 1 < NCHUNK) {
            issue(c + 1, buf ^ 1);
            asm volatile("cp.async.wait_group 1;" ::: "memory");
        } else {
            asm volatile("cp.async.wait_group 0;" ::: "memory");
        }
        __syncthreads();

        const uint32_t uA = sbase + buf * BUFSZ;
        const uint32_t uB = uA + TILE_BYTES;

        #pragma unroll
        for (int ks = 0; ks < 4; ++ks) {
            uint32_t ah[4][4];
            const int ar  = lane & 15;
            const int akb = ks * 2 + (lane >> 4);
            #pragma unroll
            for (int mt = 0; mt < 4; ++mt) {
                const int r = wm * 64 + mt * 16 + ar;
                ldsm_x4(ah[mt], uA + sw_off(r, akb));
            }
            uint32_t bh[2][4];
            #pragma unroll
            for (int p = 0; p < 2; ++p) {
                const int r  = wn * 32 + p * 16 + (lane & 7) + ((lane >> 4) & 1) * 8;
                const int kb = ks * 2 + ((lane >> 3) & 1);
                ldsm_x4(bh[p], uB + sw_off(r, kb));
            }
            #pragma unroll
            for (int mt = 0; mt < 4; ++mt)
                #pragma unroll
                for (int p = 0; p < 2; ++p)
                    #pragma unroll
                    for (int sub = 0; sub < 2; ++sub)
                        mma_fp16(acc[mt * 4 + p * 2 + sub], ah[mt],
                                 bh[p][sub * 2], bh[p][sub * 2 + 1]);
        }
        __syncthreads();
    }

    // epilogue: out += w_e(row) * acc, reduced through L2
    const int tr = lane >> 2;
    const int tc = (lane & 3) * 2;
    #pragma unroll
    for (int mt = 0; mt < 4; ++mt) {
        const int r0 = bm + wm * 64 + mt * 16 + tr;
        const float w0 = __ldg(&ew[r0 * E_DIM + e]);
        const float w1 = __ldg(&ew[(r0 + 8) * E_DIM + e]);
        float* base0 = out + (size_t)r0 * OUT_DIM + bn + wn * 32;
        float* base1 = base0 + 8 * (size_t)OUT_DIM;
        #pragma unroll
        for (int nt = 0; nt < 4; ++nt) {
            const float* a4 = acc[mt * 4 + nt];
            redadd(base0 + nt * 8 + tc,     w0 * a4[0]);
            redadd(base0 + nt * 8 + tc + 1, w0 * a4[1]);
            redadd(base1 + nt * 8 + tc,     w1 * a4[2]);
            redadd(base1 + nt * 8 + tc + 1, w1 * a4[3]);
        }
    }
}

extern "C" void kernel_launch(void* const* d_in, const int* in_sizes, int n_in,
                              void* d_out, int out_size)
{
    const float* x    = (const float*)d_in[0];   // [512, 1024]
    const float* ew   = (const float*)d_in[1];   // [512, 8]
    const float* W    = (const float*)d_in[2];   // [8, 1024, 1024]
    const float* bias = (const float*)d_in[3];   // [8, 1024]
    float* out = (float*)d_out;

    prep_kernel<<<W_BLOCKS + X_BLOCKS + O_BLOCKS, 256>>>(x, ew, W, bias, out);

    cudaFuncSetAttribute(moe_gemm_kernel,
                         cudaFuncAttributeMaxDynamicSharedMemorySize, SMEM_TOTAL);
    dim3 grid(OUT_DIM / NT, B_DIM / MT, E_DIM);   // (8, 4, 8) = 256 CTAs
    moe_gemm_kernel<<<grid, THREADS, SMEM_TOTAL>>>(ew, out);
}